// round 4
// baseline (speedup 1.0000x reference)
#include <cuda_runtime.h>
#include <cuda_fp16.h>
#include <math.h>

#define NSIDE 512
#define NPIX  (512*512)
#define NF    257

typedef unsigned long long u64;

// ---- scratch ----
__device__ __align__(16) __half2 g_tmp[NF * NPIX];  // row-pass out, [f][x][y], complex fp16
__device__ __align__(16) __half  g_m[NF * NPIX];    // modulus*512, [f][x][y], fp16
__device__ float g_gram[32 * 16 * 24];              // [group][row16][col24]; col16 = lowpass (j-groups)
__device__ float g_a2;                              // sum (512*a)^2
__device__ ulonglong2 g_twp[512];                   // packed twiddles: {(c,c),(-s,s)} for exp(+2pi i m/512)

// ---- packed f32x2 helpers ----
__device__ __forceinline__ u64 pk2(float x, float y){ u64 r; asm("mov.b64 %0,{%1,%2};":"=l"(r):"f"(x),"f"(y)); return r; }
__device__ __forceinline__ float2 up2(u64 a){ float2 v; asm("mov.b64 {%0,%1},%2;":"=f"(v.x),"=f"(v.y):"l"(a)); return v; }
__device__ __forceinline__ u64 swp(u64 a){ u64 r; asm("{.reg .b32 x,y; mov.b64 {x,y},%1; mov.b64 %0,{y,x};}":"=l"(r):"l"(a)); return r; }
__device__ __forceinline__ u64 padd(u64 a,u64 b){ u64 r; asm("add.rn.f32x2 %0,%1,%2;":"=l"(r):"l"(a),"l"(b)); return r; }
__device__ __forceinline__ u64 pmul(u64 a,u64 b){ u64 r; asm("mul.rn.f32x2 %0,%1,%2;":"=l"(r):"l"(a),"l"(b)); return r; }
__device__ __forceinline__ u64 pfma(u64 a,u64 b,u64 c){ u64 r; asm("fma.rn.f32x2 %0,%1,%2,%3;":"=l"(r):"l"(a),"l"(b),"l"(c)); return r; }

#define DECL_CONSTS \
  const u64 NEG1 = pk2(-1.f,-1.f), PIV = pk2(-1.f,1.f), MIV = pk2(1.f,-1.f); \
  const u64 CC = pk2(0.70710678118654752440f, 0.70710678118654752440f); \
  const u64 CM = pk2(-0.70710678118654752440f, -0.70710678118654752440f);

// 8-pt DFT, +i sign, natural order, packed complex
__device__ __forceinline__ void fft8p(u64 v[8], u64 NEG1, u64 PIV, u64 MIV, u64 CC, u64 CM){
  u64 es0=padd(v[0],v[4]), ed0=pfma(v[4],NEG1,v[0]);
  u64 es1=padd(v[2],v[6]), ed1=pfma(v[6],NEG1,v[2]);
  u64 E0=padd(es0,es1), E2=pfma(es1,NEG1,es0);
  u64 sd1=swp(ed1);
  u64 E1=pfma(sd1,PIV,ed0), E3=pfma(sd1,MIV,ed0);
  u64 os0=padd(v[1],v[5]), od0=pfma(v[5],NEG1,v[1]);
  u64 os1=padd(v[3],v[7]), od1=pfma(v[7],NEG1,v[3]);
  u64 O0=padd(os0,os1), O2=pfma(os1,NEG1,os0);
  u64 sod=swp(od1);
  u64 O1=pfma(sod,PIV,od0), O3=pfma(sod,MIV,od0);
  u64 O1t=pmul(pfma(swp(O1),PIV,O1), CC);          // (C(x-y), C(x+y))
  u64 O2t=pmul(swp(O2),PIV);                       // i*O2
  u64 O3t=pmul(pfma(swp(O3),MIV,O3), CM);          // (-C(x+y), C(x-y))
  v[0]=padd(E0,O0); v[4]=pfma(O0,NEG1,E0);
  v[1]=padd(E1,O1t); v[5]=pfma(O1t,NEG1,E1);
  v[2]=padd(E2,O2t); v[6]=pfma(O2t,NEG1,E2);
  v[3]=padd(E3,O3t); v[7]=pfma(O3t,NEG1,E3);
}

__device__ __forceinline__ u64 ctw(u64 a, ulonglong2 w){   // a * (c + i s)
  return pfma(swp(a), w.y, pmul(a, w.x));
}

// 8x8 transpose among lanes differing in low-3 lane bits
__device__ __forceinline__ void transpose8u(u64 v[8], int f3) {
#pragma unroll
  for (int mb = 0; mb < 3; mb++) {
    const int m = 1 << mb;
#pragma unroll
    for (int i = 0; i < 8; i++) {
      if ((i & m) == 0) {
        const int ip = i | m;
        const bool hi = (f3 & m) != 0;
        u64 send = hi ? v[i] : v[ip];
        u64 got = __shfl_xor_sync(0xffffffffu, send, m);
        if (hi) v[i] = got; else v[ip] = got;
      }
    }
  }
}

__global__ void init_kernel() {
  int t = threadIdx.x;
  for (int m = t; m < 512; m += 256) {
    float s, c;
    sincospif((float)m * (1.0f / 256.0f), &s, &c);
    g_twp[m] = make_ulonglong2(pk2(c, c), pk2(-s, s));
  }
  for (int i = t; i < 32 * 384; i += 256) g_gram[i] = 0.f;
  if (t == 0) g_a2 = 0.f;
}

// ---- stage 1: product + 512-pt IFFT along x; transposed fp16 store [f][x][y] ----
__global__ void __launch_bounds__(512) rows_kernel(const float2* __restrict__ xh2,
                                                   const float* __restrict__ pre,
                                                   const float* __restrict__ pim) {
  __shared__ u64 S[5120];
  DECL_CONSTS
  const int tid = threadIdx.x;
  const int row = tid >> 6, t = tid & 63;
  const int f = blockIdx.y;
  const int y0 = blockIdx.x << 3;
  const size_t rowoff = (size_t)(y0 + row) * NSIDE;
  const size_t fb = (size_t)f * NPIX + rowoff;

  u64 v[8];
#pragma unroll
  for (int q = 0; q < 8; q++) {
    int x = t + (q << 6);
    float2 xc = xh2[rowoff + x];
    float pr = __ldcs(pre + fb + x), pq = __ldcs(pim + fb + x);
    v[q] = pk2(xc.x * pr - xc.y * pq, xc.x * pq + xc.y * pr);
  }
  fft8p(v, NEG1, PIV, MIV, CC, CM);
  u64* Sr = S + row * 576;
  Sr[t] = v[0];
#pragma unroll
  for (int r = 1; r < 8; r++)
    Sr[r * 72 + t] = ctw(v[r], g_twp[t * r]);
  __syncthreads();

  const int r = t >> 3, T = t & 7;
#pragma unroll
  for (int q = 0; q < 8; q++)
    v[q] = Sr[r * 72 + T + (q << 3)];
  fft8p(v, NEG1, PIV, MIV, CC, CM);
#pragma unroll
  for (int rp = 1; rp < 8; rp++)
    v[rp] = ctw(v[rp], g_twp[8 * T * rp]);
  transpose8u(v, T);
  fft8p(v, NEG1, PIV, MIV, CC, CM);
  __syncthreads();

#pragma unroll
  for (int k3 = 0; k3 < 8; k3++)
    S[((k3 << 6) + t) * 10 + row] = v[k3];
  __syncthreads();

  const size_t fxb = (size_t)f * NPIX;
  const int xi = tid >> 3, yy = tid & 7;
#pragma unroll
  for (int k = 0; k < 8; k++) {
    int x = (k << 6) + xi;
    float2 b = up2(S[x * 10 + yy]);
    g_tmp[fxb + (size_t)x * NSIDE + y0 + yy] = __floats2half2_rn(b.x, b.y);
  }
}

// ---- stage 2: 512-pt IFFT along y (contiguous) + scaled modulus; a^2 for f==0 ----
__global__ void __launch_bounds__(256) cols_kernel() {
  __shared__ u64 S[4 * 576];
  __shared__ float red[8];
  DECL_CONSTS
  const int tid = threadIdx.x;
  const int cc = tid >> 6, t = tid & 63;
  const int f = blockIdx.y;
  const int x = (blockIdx.x << 2) + cc;
  const size_t colbase = (size_t)f * NPIX + (size_t)x * NSIDE;

  u64 v[8];
#pragma unroll
  for (int q = 0; q < 8; q++) {
    float2 a = __half22float2(g_tmp[colbase + t + (q << 6)]);
    v[q] = pk2(a.x, a.y);
  }
  fft8p(v, NEG1, PIV, MIV, CC, CM);
  u64* Sr = S + cc * 576;
  Sr[t] = v[0];
#pragma unroll
  for (int r = 1; r < 8; r++)
    Sr[r * 72 + t] = ctw(v[r], g_twp[t * r]);
  __syncthreads();

  const int r = t >> 3, T = t & 7;
#pragma unroll
  for (int q = 0; q < 8; q++)
    v[q] = Sr[r * 72 + T + (q << 3)];
  fft8p(v, NEG1, PIV, MIV, CC, CM);
#pragma unroll
  for (int rp = 1; rp < 8; rp++)
    v[rp] = ctw(v[rp], g_twp[8 * T * rp]);
  transpose8u(v, T);
  fft8p(v, NEG1, PIV, MIV, CC, CM);

  const float inv = 1.0f / (float)NPIX;
  float a2loc = 0.f;
#pragma unroll
  for (int k3 = 0; k3 < 8; k3++) {
    float2 a = up2(v[k3]);
    float re = a.x * inv, im = a.y * inv;
    float h = sqrtf(re * re + im * im + 1e-8f) * 512.0f;
    if (f == 0) a2loc += h * h;
    g_m[colbase + (k3 << 6) + t] = __float2half_rn(h);
  }
  if (f == 0) {
    int lane = tid & 31, wp = tid >> 5;
    a2loc += __shfl_down_sync(0xffffffffu, a2loc, 16);
    a2loc += __shfl_down_sync(0xffffffffu, a2loc, 8);
    a2loc += __shfl_down_sync(0xffffffffu, a2loc, 4);
    a2loc += __shfl_down_sync(0xffffffffu, a2loc, 2);
    a2loc += __shfl_down_sync(0xffffffffu, a2loc, 1);
    if (lane == 0) red[wp] = a2loc;
    __syncthreads();
    if (tid == 0) {
      float s = 0.f;
#pragma unroll
      for (int w2 = 0; w2 < 8; w2++) s += red[w2];
      atomicAdd(&g_a2, s);
    }
  }
}

// ---- stage 3: all grams via HMMA ----
// grid (32 groups, 32 chunks). Group g<16: j-group j=g, rows = filters 1+r*16+j, row16 = lowpass.
// g>=16: k-group k=g-16, rows = filters 1+k*16+r. Per group computes 16x16 gram (+Ea col 16 for j).
#define SB 1040     // smem row stride bytes (512 px * 2B + 16 pad)

__device__ __forceinline__ void mma16816(float c[4], unsigned a0, unsigned a1, unsigned a2,
                                         unsigned a3, unsigned b0, unsigned b1) {
  asm volatile("mma.sync.aligned.m16n8k16.row.col.f32.f16.f16.f32 "
               "{%0,%1,%2,%3}, {%4,%5,%6,%7}, {%8,%9}, {%0,%1,%2,%3};"
               : "+f"(c[0]), "+f"(c[1]), "+f"(c[2]), "+f"(c[3])
               : "r"(a0), "r"(a1), "r"(a2), "r"(a3), "r"(b0), "r"(b1));
}

__global__ void __launch_bounds__(256) gram_kernel() {
  __shared__ __align__(16) unsigned char sm[24 * SB];
  const int g = blockIdx.x;
  const int tid = threadIdx.x;
  const int w = tid >> 5, lane = tid & 31;
  const bool jg = (g < 16);
  const size_t chunkbase = (size_t)blockIdx.y * 8192;

  // zero pad rows 17..23 (lowpass n-tile padding)
  for (int i = tid; i < 7 * 65; i += 256)
    ((uint4*)(sm + 17 * SB))[i] = make_uint4(0, 0, 0, 0);

  float c0[4] = {0,0,0,0}, c1[4] = {0,0,0,0}, c2[4] = {0,0,0,0};

  const unsigned smb = (unsigned)__cvta_generic_to_shared(sm);
  const unsigned aoff = smb + ((lane & 7) + ((lane >> 3) & 1) * 8) * SB + (lane >> 4) * 16;
  const unsigned loff = smb + (16 + (lane & 7)) * SB + ((lane >> 3) & 1) * 16;
  const unsigned pwarp = w * 64 * 2;   // warp's pixel-window byte offset
  const int nrows = jg ? 17 : 16;
  __syncthreads();

  for (int it = 0; it < 16; it++) {
    const size_t P = chunkbase + it * 512;
    for (int idx = tid; idx < nrows * 64; idx += 256) {
      int rr = idx >> 6, ccc = idx & 63;
      int fidx = jg ? ((rr < 16) ? (1 + rr * 16 + g) : 0) : (1 + (g - 16) * 16 + rr);
      *(uint4*)(sm + rr * SB + ccc * 16) =
          ((const uint4*)(g_m + (size_t)fidx * NPIX + P))[ccc];
    }
    __syncthreads();

#pragma unroll
    for (int ks = 0; ks < 4; ks++) {
      unsigned pb = pwarp + ks * 32;
      unsigned a0, a1, a2, a3;
      asm volatile("ldmatrix.sync.aligned.m8n8.x4.shared.b16 {%0,%1,%2,%3}, [%4];"
                   : "=r"(a0), "=r"(a1), "=r"(a2), "=r"(a3) : "r"(aoff + pb));
      mma16816(c0, a0, a1, a2, a3, a0, a2);   // n-tile 0: filters 0-7
      mma16816(c1, a0, a1, a2, a3, a1, a3);   // n-tile 1: filters 8-15
      if (jg) {
        unsigned l0, l1;
        asm volatile("ldmatrix.sync.aligned.m8n8.x2.shared.b16 {%0,%1}, [%2];"
                     : "=r"(l0), "=r"(l1) : "r"(loff + pb));
        mma16816(c2, a0, a1, a2, a3, l0, l1); // n-tile 2: lowpass (+zero pad)
      }
    }
    __syncthreads();
  }

  // reduce 8 warps' fragments, atomicAdd to g_gram[g]
  float* Gs = (float*)sm;   // 8 * 384 floats = 12 KB, fits
  const int row0 = lane >> 2, colb = 2 * (lane & 3);
  float* W = Gs + w * 384;
  W[row0 * 24 + colb]            = c0[0];
  W[row0 * 24 + colb + 1]        = c0[1];
  W[(row0 + 8) * 24 + colb]      = c0[2];
  W[(row0 + 8) * 24 + colb + 1]  = c0[3];
  W[row0 * 24 + 8 + colb]        = c1[0];
  W[row0 * 24 + 8 + colb + 1]    = c1[1];
  W[(row0 + 8) * 24 + 8 + colb]     = c1[2];
  W[(row0 + 8) * 24 + 8 + colb + 1] = c1[3];
  W[row0 * 24 + 16 + colb]       = c2[0];
  W[row0 * 24 + 16 + colb + 1]   = c2[1];
  W[(row0 + 8) * 24 + 16 + colb]     = c2[2];
  W[(row0 + 8) * 24 + 16 + colb + 1] = c2[3];
  __syncthreads();
  for (int e = tid; e < 384; e += 256) {
    float s = 0.f;
#pragma unroll
    for (int w2 = 0; w2 < 8; w2++) s += Gs[w2 * 384 + e];
    atomicAdd(&g_gram[g * 384 + e], s);
  }
}

// ---- stage 4: assemble (reference ordering) ----
// gram entries are sums of (512 m)(512 m) -> scale 1/(NPIX * 512^2)
__global__ void assemble_kernel(float* __restrict__ out) {
  const int t = threadIdx.x;
  const float inv = 1.0f / ((float)NPIX * 262144.0f);
  if (t == 0) out[0] = g_a2 * inv;
  if (t >= 256) return;
  int i = t >> 4, j = t & 15;   // i = orientation, j = scale
  int rowsum = 152 * i + 16 * (15 * i - (i * (i - 1)) / 2);
  int segsum = 2 * j + ((i < 15) ? (15 - i) * j : 0) + 15 * j - (j * (j - 1)) / 2;
  int pos = 1 + rowsum + segsum;
  const float* GA = g_gram + (j * 16 + i) * 24;        // j-group j, row i
  out[pos++] = GA[i] * inv;        // E2[i,j]
  out[pos++] = GA[16] * inv;       // Ea[i,j]
  if (i < 15)
    for (int l = i + 1; l < 16; l++)
      out[pos++] = g_gram[(j * 16 + i) * 24 + l] * inv;          // C1[i,l,j]
  if (j < 15)
    for (int l = j + 1; l < 16; l++)
      out[pos++] = g_gram[((16 + i) * 16 + j) * 24 + l] * inv;   // C2[i,j,l]
}

extern "C" void kernel_launch(void* const* d_in, const int* in_sizes, int n_in,
                              void* d_out, int out_size) {
  const float2* xh2 = (const float2*)d_in[0];
  const float* pre  = (const float*)d_in[1];
  const float* pim  = (const float*)d_in[2];
  float* out = (float*)d_out;

  init_kernel<<<1, 256>>>();
  rows_kernel<<<dim3(NSIDE / 8, NF), 512>>>(xh2, pre, pim);
  cols_kernel<<<dim3(NSIDE / 4, NF), 256>>>();
  gram_kernel<<<dim3(32, 32), 256>>>();
  assemble_kernel<<<1, 256>>>(out);
}

// round 5
// speedup vs baseline: 1.3871x; 1.3871x over previous
#include <cuda_runtime.h>
#include <cuda_fp16.h>
#include <math.h>

#define NSIDE 512
#define NPIX  (512*512)
#define NF    257

// ---- scratch ----
__device__ __align__(16) __half2 g_tmp[NF * NPIX];  // row-pass out, [f][x][y], complex fp16
__device__ __align__(16) __half  g_m[NF * NPIX];    // modulus*512, [f][x][y], fp16
__device__ float g_gram[32 * 16 * 24];              // [group][row16][col24]; col16 = lowpass (j-groups)
__device__ float g_a2;                              // sum (512*a)^2
__device__ float2 g_tw512[512];                     // exp(+2*pi*i*m/512)

// ---- complex helpers ----
__device__ __forceinline__ float2 cadd(float2 a, float2 b){ return make_float2(a.x+b.x, a.y+b.y); }
__device__ __forceinline__ float2 csub(float2 a, float2 b){ return make_float2(a.x-b.x, a.y-b.y); }
__device__ __forceinline__ float2 cmuli(float2 a){ return make_float2(-a.y, a.x); }
__device__ __forceinline__ float2 cmul(float2 a, float2 b){
  return make_float2(a.x*b.x - a.y*b.y, a.x*b.y + a.y*b.x);
}
__device__ __forceinline__ unsigned pack_h2(float2 a){
  __half2 h = __floats2half2_rn(a.x, a.y);
  return *reinterpret_cast<unsigned*>(&h);
}

// 8-point DFT, +i sign, natural order
__device__ __forceinline__ void fft8(float2 v[8]) {
  const float C = 0.70710678118654752440f;
  float2 es0 = cadd(v[0], v[4]), ed0 = csub(v[0], v[4]);
  float2 es1 = cadd(v[2], v[6]), ed1 = csub(v[2], v[6]);
  float2 E0 = cadd(es0, es1);
  float2 E1 = cadd(ed0, cmuli(ed1));
  float2 E2 = csub(es0, es1);
  float2 E3 = csub(ed0, cmuli(ed1));
  float2 os0 = cadd(v[1], v[5]), od0 = csub(v[1], v[5]);
  float2 os1 = cadd(v[3], v[7]), od1 = csub(v[3], v[7]);
  float2 O0 = cadd(os0, os1);
  float2 O1 = cadd(od0, cmuli(od1));
  float2 O2 = csub(os0, os1);
  float2 O3 = csub(od0, cmuli(od1));
  float2 O1t = make_float2(C*(O1.x - O1.y), C*(O1.x + O1.y));
  float2 O2t = cmuli(O2);
  float2 O3t = make_float2(-C*(O3.x + O3.y), C*(O3.x - O3.y));
  v[0] = cadd(E0, O0);  v[4] = csub(E0, O0);
  v[1] = cadd(E1, O1t); v[5] = csub(E1, O1t);
  v[2] = cadd(E2, O2t); v[6] = csub(E2, O2t);
  v[3] = cadd(E3, O3t); v[7] = csub(E3, O3t);
}

// 8x8 transpose among 8 lanes differing in low-3 lane bits
__device__ __forceinline__ void transpose8(float2 v[8], int f3) {
#pragma unroll
  for (int mb = 0; mb < 3; mb++) {
    const int m = 1 << mb;
#pragma unroll
    for (int i = 0; i < 8; i++) {
      if ((i & m) == 0) {
        const int ip = i | m;
        const bool hi = (f3 & m) != 0;
        float2 send = hi ? v[i] : v[ip];
        unsigned long long u = ((unsigned long long)__float_as_uint(send.y) << 32)
                             | (unsigned long long)__float_as_uint(send.x);
        u = __shfl_xor_sync(0xffffffffu, u, m);
        float2 got = make_float2(__uint_as_float((unsigned)u),
                                 __uint_as_float((unsigned)(u >> 32)));
        if (hi) v[i] = got; else v[ip] = got;
      }
    }
  }
}

__global__ void init_kernel() {
  int t = threadIdx.x;
  for (int m = t; m < 512; m += 256) {
    float s, c;
    sincospif((float)m * (1.0f / 256.0f), &s, &c);
    g_tw512[m] = make_float2(c, s);
  }
  for (int i = t; i < 32 * 384; i += 256) g_gram[i] = 0.f;
  if (t == 0) g_a2 = 0.f;
}

// ---- stage 1: product + 512-pt IFFT along x; transposed fp16 store [f][x][y] ----
__global__ void __launch_bounds__(512) rows_kernel(const float2* __restrict__ xh2,
                                                   const float* __restrict__ pre,
                                                   const float* __restrict__ pim) {
  __shared__ float2 S[5120];
  const int tid = threadIdx.x;
  const int row = tid >> 6, t = tid & 63;
  const int f = blockIdx.y;
  const int y0 = blockIdx.x << 3;
  const size_t rowoff = (size_t)(y0 + row) * NSIDE;
  const size_t fb = (size_t)f * NPIX + rowoff;

  float2 v[8];
#pragma unroll
  for (int q = 0; q < 8; q++) {
    int x = t + (q << 6);
    float2 xc = xh2[rowoff + x];
    float pr = __ldcs(pre + fb + x), pq = __ldcs(pim + fb + x);
    v[q] = make_float2(xc.x * pr - xc.y * pq, xc.x * pq + xc.y * pr);
  }
  fft8(v);
  float2* Sr = S + row * 576;
#pragma unroll
  for (int r = 0; r < 8; r++)
    Sr[r * 72 + t] = (r == 0) ? v[0] : cmul(v[r], g_tw512[t * r]);
  __syncthreads();

  const int r = t >> 3, T = t & 7;
#pragma unroll
  for (int q = 0; q < 8; q++)
    v[q] = Sr[r * 72 + T + (q << 3)];
  fft8(v);
#pragma unroll
  for (int rp = 1; rp < 8; rp++)
    v[rp] = cmul(v[rp], g_tw512[8 * T * rp]);
  transpose8(v, T);
  fft8(v);
  __syncthreads();

#pragma unroll
  for (int k3 = 0; k3 < 8; k3++)
    S[((k3 << 6) + t) * 10 + row] = v[k3];
  __syncthreads();

  const size_t fxb = (size_t)f * NPIX;
  {
    int x = tid;
    float2 b[8];
#pragma unroll
    for (int rr = 0; rr < 8; rr++) b[rr] = S[x * 10 + rr];
    uint4 lo = make_uint4(pack_h2(b[0]), pack_h2(b[1]), pack_h2(b[2]), pack_h2(b[3]));
    uint4 hi = make_uint4(pack_h2(b[4]), pack_h2(b[5]), pack_h2(b[6]), pack_h2(b[7]));
    uint4* dst = reinterpret_cast<uint4*>(g_tmp + fxb + (size_t)x * NSIDE + y0);
    dst[0] = lo; dst[1] = hi;
  }
}

// ---- stage 2: 512-pt IFFT along y (contiguous) + scaled modulus; a^2 for f==0 ----
__global__ void __launch_bounds__(256) cols_kernel() {
  __shared__ float2 S[4 * 576];
  __shared__ float red[8];
  const int tid = threadIdx.x;
  const int cc = tid >> 6, t = tid & 63;
  const int f = blockIdx.y;
  const int x = (blockIdx.x << 2) + cc;
  const size_t colbase = (size_t)f * NPIX + (size_t)x * NSIDE;

  float2 v[8];
#pragma unroll
  for (int q = 0; q < 8; q++)
    v[q] = __half22float2(g_tmp[colbase + t + (q << 6)]);
  fft8(v);
  float2* Sr = S + cc * 576;
#pragma unroll
  for (int r = 0; r < 8; r++)
    Sr[r * 72 + t] = (r == 0) ? v[0] : cmul(v[r], g_tw512[t * r]);
  __syncthreads();

  const int r = t >> 3, T = t & 7;
#pragma unroll
  for (int q = 0; q < 8; q++)
    v[q] = Sr[r * 72 + T + (q << 3)];
  fft8(v);
#pragma unroll
  for (int rp = 1; rp < 8; rp++)
    v[rp] = cmul(v[rp], g_tw512[8 * T * rp]);
  transpose8(v, T);
  fft8(v);

  const float inv = 1.0f / (float)NPIX;
  float a2loc = 0.f;
#pragma unroll
  for (int k3 = 0; k3 < 8; k3++) {
    float re = v[k3].x * inv, im = v[k3].y * inv;
    float h = sqrtf(re * re + im * im + 1e-8f) * 512.0f;
    if (f == 0) a2loc += h * h;
    g_m[colbase + (k3 << 6) + t] = __float2half_rn(h);
  }
  if (f == 0) {
    int lane = tid & 31, wp = tid >> 5;
    a2loc += __shfl_down_sync(0xffffffffu, a2loc, 16);
    a2loc += __shfl_down_sync(0xffffffffu, a2loc, 8);
    a2loc += __shfl_down_sync(0xffffffffu, a2loc, 4);
    a2loc += __shfl_down_sync(0xffffffffu, a2loc, 2);
    a2loc += __shfl_down_sync(0xffffffffu, a2loc, 1);
    if (lane == 0) red[wp] = a2loc;
    __syncthreads();
    if (tid == 0) {
      float s = 0.f;
#pragma unroll
      for (int w2 = 0; w2 < 8; w2++) s += red[w2];
      atomicAdd(&g_a2, s);
    }
  }
}

// ---- stage 3: all grams via HMMA, double-buffered pipeline ----
#define SB 1040     // smem row stride bytes (512 px * 2B + 16 pad)

__device__ __forceinline__ void mma16816(float c[4], unsigned a0, unsigned a1, unsigned a2,
                                         unsigned a3, unsigned b0, unsigned b1) {
  asm volatile("mma.sync.aligned.m16n8k16.row.col.f32.f16.f16.f32 "
               "{%0,%1,%2,%3}, {%4,%5,%6,%7}, {%8,%9}, {%0,%1,%2,%3};"
               : "+f"(c[0]), "+f"(c[1]), "+f"(c[2]), "+f"(c[3])
               : "r"(a0), "r"(a1), "r"(a2), "r"(a3), "r"(b0), "r"(b1));
}

__global__ void __launch_bounds__(256) gram_kernel() {
  __shared__ __align__(16) unsigned char sm[2][24 * SB];   // ~49 KB
  const int g = blockIdx.x;
  const int tid = threadIdx.x;
  const int w = tid >> 5, lane = tid & 31;
  const bool jg = (g < 16);
  const size_t chunkbase = (size_t)blockIdx.y * 8192;

  // zero pad rows 17..23 of both buffers (lowpass n-tile padding; never overwritten)
  for (int i = tid; i < 7 * 65; i += 256) {
    ((uint4*)(sm[0] + 17 * SB))[i] = make_uint4(0, 0, 0, 0);
    ((uint4*)(sm[1] + 17 * SB))[i] = make_uint4(0, 0, 0, 0);
  }

  // per-thread source rows: p=0..3 -> row (tid>>6)+4p, col (tid&63); p=4 -> lowpass row16 (tid<64)
  const int ccc = tid & 63, rbase = tid >> 6;
  const uint4* src[5];
#pragma unroll
  for (int p = 0; p < 4; p++) {
    int rr = rbase + 4 * p;
    int fidx = jg ? (1 + rr * 16 + g) : (1 + (g - 16) * 16 + rr);
    src[p] = (const uint4*)(g_m + (size_t)fidx * NPIX) + ccc;
  }
  src[4] = (const uint4*)g_m + tid;  // lowpass, threads 0..63
  const bool do_lp = jg && (tid < 64);

  float c0[4] = {0,0,0,0}, c1[4] = {0,0,0,0}, c2[4] = {0,0,0,0};

  unsigned smb[2] = { (unsigned)__cvta_generic_to_shared(sm[0]),
                      (unsigned)__cvta_generic_to_shared(sm[1]) };
  const unsigned arel = ((lane & 7) + ((lane >> 3) & 1) * 8) * SB + (lane >> 4) * 16;
  const unsigned lrel = (16 + (lane & 7)) * SB + ((lane >> 3) & 1) * 16;
  const unsigned pwarp = w * 128;    // warp's 64-px window byte offset
  const unsigned dst0 = rbase * SB + ccc * 16;

  uint4 rg[5];
  // prologue: load chunk 0 -> buf 0
  {
    const size_t P4 = chunkbase >> 3;   // uint4 index offset (8 halves per uint4)
#pragma unroll
    for (int p = 0; p < 4; p++) rg[p] = src[p][P4];
    if (do_lp) rg[4] = src[4][P4];
#pragma unroll
    for (int p = 0; p < 4; p++)
      *(uint4*)(sm[0] + dst0 + p * 4 * SB) = rg[p];
    if (do_lp) *(uint4*)(sm[0] + 16 * SB + tid * 16) = rg[4];
  }
  __syncthreads();

  for (int it = 0; it < 16; it++) {
    const int b = it & 1;
    if (it < 15) {
      const size_t P4 = (chunkbase + (it + 1) * 512) >> 3;
#pragma unroll
      for (int p = 0; p < 4; p++) rg[p] = src[p][P4];
      if (do_lp) rg[4] = src[4][P4];
    }

#pragma unroll
    for (int ks = 0; ks < 4; ks++) {
      unsigned pb = pwarp + ks * 32;
      unsigned a0, a1, a2, a3;
      asm volatile("ldmatrix.sync.aligned.m8n8.x4.shared.b16 {%0,%1,%2,%3}, [%4];"
                   : "=r"(a0), "=r"(a1), "=r"(a2), "=r"(a3) : "r"(smb[b] + arel + pb));
      mma16816(c0, a0, a1, a2, a3, a0, a2);
      mma16816(c1, a0, a1, a2, a3, a1, a3);
      if (jg) {
        unsigned l0, l1;
        asm volatile("ldmatrix.sync.aligned.m8n8.x2.shared.b16 {%0,%1}, [%2];"
                     : "=r"(l0), "=r"(l1) : "r"(smb[b] + lrel + pb));
        mma16816(c2, a0, a1, a2, a3, l0, l1);
      }
    }

    if (it < 15) {
      unsigned char* dbuf = sm[1 - b];
#pragma unroll
      for (int p = 0; p < 4; p++)
        *(uint4*)(dbuf + dst0 + p * 4 * SB) = rg[p];
      if (do_lp) *(uint4*)(dbuf + 16 * SB + tid * 16) = rg[4];
    }
    __syncthreads();
  }

  // reduce 8 warps' fragments, atomicAdd to g_gram[g]
  float* Gs = (float*)sm;   // 12 KB scratch
  const int row0 = lane >> 2, colb = 2 * (lane & 3);
  float* W = Gs + w * 384;
  W[row0 * 24 + colb]            = c0[0];
  W[row0 * 24 + colb + 1]        = c0[1];
  W[(row0 + 8) * 24 + colb]      = c0[2];
  W[(row0 + 8) * 24 + colb + 1]  = c0[3];
  W[row0 * 24 + 8 + colb]        = c1[0];
  W[row0 * 24 + 8 + colb + 1]    = c1[1];
  W[(row0 + 8) * 24 + 8 + colb]     = c1[2];
  W[(row0 + 8) * 24 + 8 + colb + 1] = c1[3];
  W[row0 * 24 + 16 + colb]       = c2[0];
  W[row0 * 24 + 16 + colb + 1]   = c2[1];
  W[(row0 + 8) * 24 + 16 + colb]     = c2[2];
  W[(row0 + 8) * 24 + 16 + colb + 1] = c2[3];
  __syncthreads();
  for (int e = tid; e < 384; e += 256) {
    float s = 0.f;
#pragma unroll
    for (int w2 = 0; w2 < 8; w2++) s += Gs[w2 * 384 + e];
    atomicAdd(&g_gram[g * 384 + e], s);
  }
}

// ---- stage 4: assemble (reference ordering); scale 1/(NPIX*512^2) ----
__global__ void assemble_kernel(float* __restrict__ out) {
  const int t = threadIdx.x;
  const float inv = 1.0f / ((float)NPIX * 262144.0f);
  if (t == 0) out[0] = g_a2 * inv;
  if (t >= 256) return;
  int i = t >> 4, j = t & 15;
  int rowsum = 152 * i + 16 * (15 * i - (i * (i - 1)) / 2);
  int segsum = 2 * j + ((i < 15) ? (15 - i) * j : 0) + 15 * j - (j * (j - 1)) / 2;
  int pos = 1 + rowsum + segsum;
  const float* GA = g_gram + (j * 16 + i) * 24;
  out[pos++] = GA[i] * inv;        // E2[i,j]
  out[pos++] = GA[16] * inv;       // Ea[i,j]
  if (i < 15)
    for (int l = i + 1; l < 16; l++)
      out[pos++] = g_gram[(j * 16 + i) * 24 + l] * inv;          // C1[i,l,j]
  if (j < 15)
    for (int l = j + 1; l < 16; l++)
      out[pos++] = g_gram[((16 + i) * 16 + j) * 24 + l] * inv;   // C2[i,j,l]
}

extern "C" void kernel_launch(void* const* d_in, const int* in_sizes, int n_in,
                              void* d_out, int out_size) {
  const float2* xh2 = (const float2*)d_in[0];
  const float* pre  = (const float*)d_in[1];
  const float* pim  = (const float*)d_in[2];
  float* out = (float*)d_out;

  init_kernel<<<1, 256>>>();
  rows_kernel<<<dim3(NSIDE / 8, NF), 512>>>(xh2, pre, pim);
  cols_kernel<<<dim3(NSIDE / 4, NF), 256>>>();
  gram_kernel<<<dim3(32, 32), 256>>>();
  assemble_kernel<<<1, 256>>>(out);
}

// round 6
// speedup vs baseline: 1.5649x; 1.1281x over previous
#include <cuda_runtime.h>
#include <cuda_fp16.h>
#include <math.h>

#define NSIDE 512
#define NPIX  (512*512)
#define NF    257

typedef __half2 h2;

// ---- scratch ----
__device__ __align__(16) h2     g_tmp[NF * NPIX];  // row-pass out, [f][x][y], complex fp16
__device__ __align__(16) __half g_m[NF * NPIX];    // modulus*512, [f][x][y], fp16
__device__ float g_gram[32 * 16 * 24];             // [group][row16][col24]; col16 = lowpass
__device__ float g_a2;                             // sum (512*a)^2
__device__ uint2 g_twh[512];                       // packed fp16 twiddles {(c,c),(-s,s)}

// ---- half2 complex helpers ----
__device__ __forceinline__ h2 hswap(h2 a){ return __lowhigh2highlow(a); }
__device__ __forceinline__ unsigned h2u(h2 a){ return *reinterpret_cast<unsigned*>(&a); }
__device__ __forceinline__ h2 u2h(unsigned a){ return *reinterpret_cast<h2*>(&a); }

#define DECL_H_CONSTS \
  const h2 PI2 = __floats2half2_rn(-1.f, 1.f);  /* mul by this after swap => *i   */ \
  const h2 MI2 = __floats2half2_rn(1.f, -1.f);  /*                        => *-i  */ \
  const h2 CCh = __floats2half2_rn(0.70710678118654752440f, 0.70710678118654752440f); \
  const h2 NCC = __floats2half2_rn(-0.70710678118654752440f, 0.70710678118654752440f);

// 8-pt DFT, +i sign, natural order, half2 complex
__device__ __forceinline__ void fft8h(h2 v[8], h2 PI2, h2 MI2, h2 CCh, h2 NCC) {
  h2 es0 = __hadd2(v[0], v[4]), ed0 = __hsub2(v[0], v[4]);
  h2 es1 = __hadd2(v[2], v[6]), ed1 = __hsub2(v[2], v[6]);
  h2 E0 = __hadd2(es0, es1), E2 = __hsub2(es0, es1);
  h2 sd1 = hswap(ed1);
  h2 E1 = __hfma2(sd1, PI2, ed0);   // ed0 + i*ed1
  h2 E3 = __hfma2(sd1, MI2, ed0);   // ed0 - i*ed1
  h2 os0 = __hadd2(v[1], v[5]), od0 = __hsub2(v[1], v[5]);
  h2 os1 = __hadd2(v[3], v[7]), od1 = __hsub2(v[3], v[7]);
  h2 O0 = __hadd2(os0, os1), O2 = __hsub2(os0, os1);
  h2 sod = hswap(od1);
  h2 O1 = __hfma2(sod, PI2, od0);
  h2 O3 = __hfma2(sod, MI2, od0);
  h2 t1 = __hfma2(hswap(O1), PI2, O1);     // (x-y, x+y)
  h2 O1t = __hmul2(t1, CCh);               // (C(x-y), C(x+y))
  h2 O2t = __hmul2(hswap(O2), PI2);        // i*O2
  h2 t2 = __hfma2(hswap(O3), PI2, O3);     // (x-y, x+y)
  h2 O3t = __hmul2(hswap(t2), NCC);        // (-C(x+y), C(x-y))
  v[0] = __hadd2(E0, O0);  v[4] = __hsub2(E0, O0);
  v[1] = __hadd2(E1, O1t); v[5] = __hsub2(E1, O1t);
  v[2] = __hadd2(E2, O2t); v[6] = __hsub2(E2, O2t);
  v[3] = __hadd2(E3, O3t); v[7] = __hsub2(E3, O3t);
}

__device__ __forceinline__ h2 ctwh(h2 a, uint2 w) {   // a * (c + i s)
  return __hfma2(hswap(a), u2h(w.y), __hmul2(a, u2h(w.x)));
}

// 8x8 transpose among 8 lanes differing in low-3 lane bits (32-bit shuffles)
__device__ __forceinline__ void transpose8h(h2 v[8], int f3) {
#pragma unroll
  for (int mb = 0; mb < 3; mb++) {
    const int m = 1 << mb;
#pragma unroll
    for (int i = 0; i < 8; i++) {
      if ((i & m) == 0) {
        const int ip = i | m;
        const bool hi = (f3 & m) != 0;
        unsigned send = h2u(hi ? v[i] : v[ip]);
        unsigned got = __shfl_xor_sync(0xffffffffu, send, m);
        if (hi) v[i] = u2h(got); else v[ip] = u2h(got);
      }
    }
  }
}

__global__ void init_kernel() {
  int t = threadIdx.x;
  for (int m = t; m < 512; m += 256) {
    float s, c;
    sincospif((float)m * (1.0f / 256.0f), &s, &c);
    h2 wc = __floats2half2_rn(c, c), ws = __floats2half2_rn(-s, s);
    g_twh[m] = make_uint2(*reinterpret_cast<unsigned*>(&wc), *reinterpret_cast<unsigned*>(&ws));
  }
  for (int i = t; i < 32 * 384; i += 256) g_gram[i] = 0.f;
  if (t == 0) g_a2 = 0.f;
}

// ---- stage 1: product + 512-pt IFFT along x (fp16); transposed store [f][x][y] ----
__global__ void __launch_bounds__(512) rows_kernel(const float2* __restrict__ xh2,
                                                   const float* __restrict__ pre,
                                                   const float* __restrict__ pim) {
  __shared__ h2 S[5120];   // 20 KB: FFT stage 8*576; transpose stage stride 9
  DECL_H_CONSTS
  const int tid = threadIdx.x;
  const int row = tid >> 6, t = tid & 63;
  const int f = blockIdx.y;
  const int y0 = blockIdx.x << 3;
  const size_t rowoff = (size_t)(y0 + row) * NSIDE;
  const size_t fb = (size_t)f * NPIX + rowoff;

  h2 v[8];
#pragma unroll
  for (int q = 0; q < 8; q++) {
    int x = t + (q << 6);
    float2 xc = xh2[rowoff + x];
    float pr = __ldcs(pre + fb + x), pq = __ldcs(pim + fb + x);
    v[q] = __floats2half2_rn(xc.x * pr - xc.y * pq, xc.x * pq + xc.y * pr);
  }
  fft8h(v, PI2, MI2, CCh, NCC);
  h2* Sr = S + row * 576;
  Sr[t] = v[0];
#pragma unroll
  for (int r = 1; r < 8; r++)
    Sr[r * 72 + t] = ctwh(v[r], g_twh[t * r]);
  __syncthreads();

  const int r = t >> 3, T = t & 7;
#pragma unroll
  for (int q = 0; q < 8; q++)
    v[q] = Sr[r * 72 + T + (q << 3)];
  fft8h(v, PI2, MI2, CCh, NCC);
#pragma unroll
  for (int rp = 1; rp < 8; rp++)
    v[rp] = ctwh(v[rp], g_twh[8 * T * rp]);
  transpose8h(v, T);
  fft8h(v, PI2, MI2, CCh, NCC);
  __syncthreads();

#pragma unroll
  for (int k3 = 0; k3 < 8; k3++)
    S[((k3 << 6) + t) * 9 + row] = v[k3];
  __syncthreads();

  const size_t fxb = (size_t)f * NPIX;
  {
    int x = tid;
    uint4 lo = make_uint4(h2u(S[x*9+0]), h2u(S[x*9+1]), h2u(S[x*9+2]), h2u(S[x*9+3]));
    uint4 hi = make_uint4(h2u(S[x*9+4]), h2u(S[x*9+5]), h2u(S[x*9+6]), h2u(S[x*9+7]));
    uint4* dst = reinterpret_cast<uint4*>(g_tmp + fxb + (size_t)x * NSIDE + y0);
    dst[0] = lo; dst[1] = hi;
  }
}

// ---- stage 2: 512-pt IFFT along y (fp16, contiguous) + scaled modulus; a^2 for f==0 ----
__global__ void __launch_bounds__(256) cols_kernel() {
  __shared__ h2 S[4 * 576];
  __shared__ float red[8];
  DECL_H_CONSTS
  const int tid = threadIdx.x;
  const int cc = tid >> 6, t = tid & 63;
  const int f = blockIdx.y;
  const int x = (blockIdx.x << 2) + cc;
  const size_t colbase = (size_t)f * NPIX + (size_t)x * NSIDE;

  h2 v[8];
#pragma unroll
  for (int q = 0; q < 8; q++)
    v[q] = g_tmp[colbase + t + (q << 6)];
  fft8h(v, PI2, MI2, CCh, NCC);
  h2* Sr = S + cc * 576;
  Sr[t] = v[0];
#pragma unroll
  for (int r = 1; r < 8; r++)
    Sr[r * 72 + t] = ctwh(v[r], g_twh[t * r]);
  __syncthreads();

  const int r = t >> 3, T = t & 7;
#pragma unroll
  for (int q = 0; q < 8; q++)
    v[q] = Sr[r * 72 + T + (q << 3)];
  fft8h(v, PI2, MI2, CCh, NCC);
#pragma unroll
  for (int rp = 1; rp < 8; rp++)
    v[rp] = ctwh(v[rp], g_twh[8 * T * rp]);
  transpose8h(v, T);
  fft8h(v, PI2, MI2, CCh, NCC);

  const float inv = 1.0f / (float)NPIX;
  float a2loc = 0.f;
#pragma unroll
  for (int k3 = 0; k3 < 8; k3++) {
    float2 a = __half22float2(v[k3]);
    float re = a.x * inv, im = a.y * inv;
    float h = sqrtf(re * re + im * im + 1e-8f) * 512.0f;
    if (f == 0) a2loc += h * h;
    g_m[colbase + (k3 << 6) + t] = __float2half_rn(h);
  }
  if (f == 0) {
    int lane = tid & 31, wp = tid >> 5;
    a2loc += __shfl_down_sync(0xffffffffu, a2loc, 16);
    a2loc += __shfl_down_sync(0xffffffffu, a2loc, 8);
    a2loc += __shfl_down_sync(0xffffffffu, a2loc, 4);
    a2loc += __shfl_down_sync(0xffffffffu, a2loc, 2);
    a2loc += __shfl_down_sync(0xffffffffu, a2loc, 1);
    if (lane == 0) red[wp] = a2loc;
    __syncthreads();
    if (tid == 0) {
      float s = 0.f;
#pragma unroll
      for (int w2 = 0; w2 < 8; w2++) s += red[w2];
      atomicAdd(&g_a2, s);
    }
  }
}

// ---- stage 3: all grams via HMMA, double-buffered pipeline ----
#define SB 1040

__device__ __forceinline__ void mma16816(float c[4], unsigned a0, unsigned a1, unsigned a2,
                                         unsigned a3, unsigned b0, unsigned b1) {
  asm volatile("mma.sync.aligned.m16n8k16.row.col.f32.f16.f16.f32 "
               "{%0,%1,%2,%3}, {%4,%5,%6,%7}, {%8,%9}, {%0,%1,%2,%3};"
               : "+f"(c[0]), "+f"(c[1]), "+f"(c[2]), "+f"(c[3])
               : "r"(a0), "r"(a1), "r"(a2), "r"(a3), "r"(b0), "r"(b1));
}

__global__ void __launch_bounds__(256) gram_kernel() {
  __shared__ __align__(16) unsigned char sm[2][24 * SB];
  const int g = blockIdx.x;
  const int tid = threadIdx.x;
  const int w = tid >> 5, lane = tid & 31;
  const bool jg = (g < 16);
  const size_t chunkbase = (size_t)blockIdx.y * 8192;

  for (int i = tid; i < 7 * 65; i += 256) {
    ((uint4*)(sm[0] + 17 * SB))[i] = make_uint4(0, 0, 0, 0);
    ((uint4*)(sm[1] + 17 * SB))[i] = make_uint4(0, 0, 0, 0);
  }

  const int ccc = tid & 63, rbase = tid >> 6;
  const uint4* src[5];
#pragma unroll
  for (int p = 0; p < 4; p++) {
    int rr = rbase + 4 * p;
    int fidx = jg ? (1 + rr * 16 + g) : (1 + (g - 16) * 16 + rr);
    src[p] = (const uint4*)(g_m + (size_t)fidx * NPIX) + ccc;
  }
  src[4] = (const uint4*)g_m + tid;
  const bool do_lp = jg && (tid < 64);

  float c0[4] = {0,0,0,0}, c1[4] = {0,0,0,0}, c2[4] = {0,0,0,0};

  unsigned smb[2] = { (unsigned)__cvta_generic_to_shared(sm[0]),
                      (unsigned)__cvta_generic_to_shared(sm[1]) };
  const unsigned arel = ((lane & 7) + ((lane >> 3) & 1) * 8) * SB + (lane >> 4) * 16;
  const unsigned lrel = (16 + (lane & 7)) * SB + ((lane >> 3) & 1) * 16;
  const unsigned pwarp = w * 128;
  const unsigned dst0 = rbase * SB + ccc * 16;

  uint4 rg[5];
  {
    const size_t P4 = chunkbase >> 3;
#pragma unroll
    for (int p = 0; p < 4; p++) rg[p] = src[p][P4];
    if (do_lp) rg[4] = src[4][P4];
#pragma unroll
    for (int p = 0; p < 4; p++)
      *(uint4*)(sm[0] + dst0 + p * 4 * SB) = rg[p];
    if (do_lp) *(uint4*)(sm[0] + 16 * SB + tid * 16) = rg[4];
  }
  __syncthreads();

  for (int it = 0; it < 16; it++) {
    const int b = it & 1;
    if (it < 15) {
      const size_t P4 = (chunkbase + (it + 1) * 512) >> 3;
#pragma unroll
      for (int p = 0; p < 4; p++) rg[p] = src[p][P4];
      if (do_lp) rg[4] = src[4][P4];
    }

#pragma unroll
    for (int ks = 0; ks < 4; ks++) {
      unsigned pb = pwarp + ks * 32;
      unsigned a0, a1, a2, a3;
      asm volatile("ldmatrix.sync.aligned.m8n8.x4.shared.b16 {%0,%1,%2,%3}, [%4];"
                   : "=r"(a0), "=r"(a1), "=r"(a2), "=r"(a3) : "r"(smb[b] + arel + pb));
      mma16816(c0, a0, a1, a2, a3, a0, a2);
      mma16816(c1, a0, a1, a2, a3, a1, a3);
      if (jg) {
        unsigned l0, l1;
        asm volatile("ldmatrix.sync.aligned.m8n8.x2.shared.b16 {%0,%1}, [%2];"
                     : "=r"(l0), "=r"(l1) : "r"(smb[b] + lrel + pb));
        mma16816(c2, a0, a1, a2, a3, l0, l1);
      }
    }

    if (it < 15) {
      unsigned char* dbuf = sm[1 - b];
#pragma unroll
      for (int p = 0; p < 4; p++)
        *(uint4*)(dbuf + dst0 + p * 4 * SB) = rg[p];
      if (do_lp) *(uint4*)(dbuf + 16 * SB + tid * 16) = rg[4];
    }
    __syncthreads();
  }

  float* Gs = (float*)sm;
  const int row0 = lane >> 2, colb = 2 * (lane & 3);
  float* W = Gs + w * 384;
  W[row0 * 24 + colb]            = c0[0];
  W[row0 * 24 + colb + 1]        = c0[1];
  W[(row0 + 8) * 24 + colb]      = c0[2];
  W[(row0 + 8) * 24 + colb + 1]  = c0[3];
  W[row0 * 24 + 8 + colb]        = c1[0];
  W[row0 * 24 + 8 + colb + 1]    = c1[1];
  W[(row0 + 8) * 24 + 8 + colb]     = c1[2];
  W[(row0 + 8) * 24 + 8 + colb + 1] = c1[3];
  W[row0 * 24 + 16 + colb]       = c2[0];
  W[row0 * 24 + 16 + colb + 1]   = c2[1];
  W[(row0 + 8) * 24 + 16 + colb]     = c2[2];
  W[(row0 + 8) * 24 + 16 + colb + 1] = c2[3];
  __syncthreads();
  for (int e = tid; e < 384; e += 256) {
    float s = 0.f;
#pragma unroll
    for (int w2 = 0; w2 < 8; w2++) s += Gs[w2 * 384 + e];
    atomicAdd(&g_gram[g * 384 + e], s);
  }
}

// ---- stage 4: assemble (reference ordering); scale 1/(NPIX*512^2) ----
__global__ void assemble_kernel(float* __restrict__ out) {
  const int t = threadIdx.x;
  const float inv = 1.0f / ((float)NPIX * 262144.0f);
  if (t == 0) out[0] = g_a2 * inv;
  if (t >= 256) return;
  int i = t >> 4, j = t & 15;
  int rowsum = 152 * i + 16 * (15 * i - (i * (i - 1)) / 2);
  int segsum = 2 * j + ((i < 15) ? (15 - i) * j : 0) + 15 * j - (j * (j - 1)) / 2;
  int pos = 1 + rowsum + segsum;
  const float* GA = g_gram + (j * 16 + i) * 24;
  out[pos++] = GA[i] * inv;
  out[pos++] = GA[16] * inv;
  if (i < 15)
    for (int l = i + 1; l < 16; l++)
      out[pos++] = g_gram[(j * 16 + i) * 24 + l] * inv;
  if (j < 15)
    for (int l = j + 1; l < 16; l++)
      out[pos++] = g_gram[((16 + i) * 16 + j) * 24 + l] * inv;
}

extern "C" void kernel_launch(void* const* d_in, const int* in_sizes, int n_in,
                              void* d_out, int out_size) {
  const float2* xh2 = (const float2*)d_in[0];
  const float* pre  = (const float*)d_in[1];
  const float* pim  = (const float*)d_in[2];
  float* out = (float*)d_out;

  init_kernel<<<1, 256>>>();
  rows_kernel<<<dim3(NSIDE / 8, NF), 512>>>(xh2, pre, pim);
  cols_kernel<<<dim3(NSIDE / 4, NF), 256>>>();
  gram_kernel<<<dim3(32, 32), 256>>>();
  assemble_kernel<<<1, 256>>>(out);
}